// round 2
// baseline (speedup 1.0000x reference)
#include <cuda_runtime.h>
#include <cstdint>

#define HB   4
#define CIN  256
#define HID  16
#define IMGH 192
#define IMGW 192
#define HW   (IMGH*IMGW)        // 36864
#define COUT 128
#define CCAT 288

#define FMA2(acc,a,b)  asm("fma.rn.f32x2 %0, %1, %2, %0;" : "+l"(acc) : "l"(a), "l"(b))
#define PACK2(d,lo,hi) asm("mov.b64 %0, {%1, %2};" : "=l"(d) : "f"(lo), "f"(hi))
#define UNPACK2(lo,hi,s) asm("mov.b64 {%0, %1}, %2;" : "=f"(lo), "=f"(hi) : "l"(s))

// ---------------- scratch (device globals; no allocation) ----------------
__device__ float g_h[2][HB*HID*HW];        // h0, h1
__device__ float g_cat[HB*CCAT*HW];        // branch outputs concatenated
__device__ float g_w2p[CIN*288];           // 3x3 weights: [ci][o][t][dup2]

__constant__ int c_dy[9] = {-1,-1,-1, 0, 1, 1, 1, 0, 0};
__constant__ int c_dx[9] = {-1, 0, 1, 1, 1, 0,-1,-1, 0};

// ---------------- prep: repack 3x3 weights, duplicated pairs --------------
__global__ void k_prep(const float* __restrict__ w)
{
    int idx = blockIdx.x*256 + threadIdx.x;      // 0 .. 256*288
    if (idx >= CIN*288) return;
    int rem = idx % 288;
    int ci  = idx / 288;
    int o   = rem / 18;
    int t   = (rem % 18) >> 1;
    g_w2p[idx] = w[(o*CIN + ci)*9 + t];          // in_w1[o][ci][ky][kx], dup 2x
}

// ---------------- K1: 1x1 conv 256->16 (+bias) -> g_h[0] ----------------
__global__ void k_conv1x1(const float* __restrict__ cen,
                          const float* __restrict__ w,
                          const float* __restrict__ bias)
{
    __shared__ float ws[CIN*16];                 // ws[i][o]
    int tid = threadIdx.x;
    for (int j = tid; j < CIN*16; j += 256) {
        int o = j >> 8, i = j & 255;
        ws[i*16 + o] = w[j];
    }
    __syncthreads();

    int gid = blockIdx.x*256 + tid;
    int bb = gid / HW, p = gid % HW;
    const float* cp = cen + (size_t)bb*CIN*HW + p;

    float acc[16];
    #pragma unroll
    for (int o = 0; o < 16; o++) acc[o] = bias[o];

    for (int i = 0; i < CIN; i++) {
        float v = __ldg(&cp[(size_t)i*HW]);
        const float4* wr = (const float4*)&ws[i*16];
        #pragma unroll
        for (int o4 = 0; o4 < 4; o4++) {
            float4 wv = wr[o4];
            acc[o4*4+0] += v*wv.x;
            acc[o4*4+1] += v*wv.y;
            acc[o4*4+2] += v*wv.z;
            acc[o4*4+3] += v*wv.w;
        }
    }
    float* hp = g_h[0] + (size_t)bb*HID*HW + p;
    #pragma unroll
    for (int o = 0; o < 16; o++) hp[(size_t)o*HW] = acc[o];
}

// ---------------- K2: 3x3 conv 256->16 (+bias), SAME pad -> g_h[1] ------
// block (16,16); tile 64x16 pixels; 4 x-adjacent pixels/thread; f32x2 FMA.
__global__ void __launch_bounds__(256)
k_conv3x3(const float* __restrict__ cen,
          const float* __restrict__ bias)
{
    __shared__ float tile[18][68];               // (16+2) x (64+2) pad->68
    __shared__ float wch[288];                   // [o][t][dup2] for one ci
    int tx = threadIdx.x, ty = threadIdx.y;
    int tid = ty*16 + tx;
    int x0 = blockIdx.x*64 - 1;
    int y0 = blockIdx.y*16 - 1;
    int bz = blockIdx.z;

    unsigned long long accA[16], accB[16];       // (px0,px1), (px2,px3)
    #pragma unroll
    for (int o = 0; o < 16; o++) { accA[o] = 0ull; accB[o] = 0ull; }

    const float* cb = cen + (size_t)bz*CIN*HW;

    for (int ci = 0; ci < CIN; ci++) {
        __syncthreads();
        const float* cc = cb + (size_t)ci*HW;
        for (int j = tid; j < 18*66; j += 256) {
            int r = j / 66, c = j - r*66;
            int gy = y0 + r, gx = x0 + c;
            float v = 0.f;
            if ((unsigned)gy < (unsigned)IMGH && (unsigned)gx < (unsigned)IMGW)
                v = __ldg(&cc[gy*IMGW + gx]);
            tile[r][c] = v;
        }
        for (int j = tid; j < 288; j += 256) wch[j] = g_w2p[ci*288 + j];
        __syncthreads();

        // x pairs per row: P0..P4 covering cols 4tx .. 4tx+5
        unsigned long long pr[3][5];
        #pragma unroll
        for (int r = 0; r < 3; r++) {
            const float* trp = &tile[ty+r][4*tx];
            float4 f  = *(const float4*)trp;
            float2 g2 = *(const float2*)(trp + 4);
            PACK2(pr[r][0], f.x, f.y);
            PACK2(pr[r][1], f.y, f.z);
            PACK2(pr[r][2], f.z, f.w);
            PACK2(pr[r][3], f.w, g2.x);
            PACK2(pr[r][4], g2.x, g2.y);
        }
        #pragma unroll
        for (int o = 0; o < 16; o++) {
            const unsigned long long* wp = (const unsigned long long*)&wch[o*18];
            #pragma unroll
            for (int r = 0; r < 3; r++) {
                #pragma unroll
                for (int k = 0; k < 3; k++) {
                    unsigned long long wv = wp[r*3+k];
                    FMA2(accA[o], wv, pr[r][k]);
                    FMA2(accB[o], wv, pr[r][k+2]);
                }
            }
        }
    }

    int gx = blockIdx.x*64 + 4*tx;
    int gy = y0 + 1 + ty;
    float* hp = g_h[1] + (size_t)bz*HID*HW + gy*IMGW + gx;
    #pragma unroll
    for (int o = 0; o < 16; o++) {
        float a0,a1,a2,a3;
        UNPACK2(a0, a1, accA[o]);
        UNPACK2(a2, a3, accB[o]);
        float bv = __ldg(&bias[o]);
        float4 v = make_float4(a0+bv, a1+bv, a2+bv, a3+bv);
        *(float4*)&hp[(size_t)o*HW] = v;
    }
}

// ---------------- K3/K4: branch (shift attention), quad-per-pixel --------
// 128 threads = 32 pixels; 4 threads/pixel, each owns 4 channels.
// v1/v3 in registers, h shared via quad shfl, logits via bfly reduce.
__global__ void __launch_bounds__(128, 3)
k_branch(int which,
         const float* __restrict__ w1, const float* __restrict__ w2,
         const float* __restrict__ w3, const float* __restrict__ scale,
         int sidx, int shift, int cbase)
{
    // transposed weights: dst[g][c4][d][j] = src[g][d][c4*4+j]
    __shared__ float ws1[2304], ws2[2304], ws3[2304];
    int tid = threadIdx.x;
    for (int idx = tid; idx < 2304; idx += 128) {
        int g  = idx >> 8, rem = idx & 255;
        int c4 = rem >> 6, r2  = rem & 63;
        int d  = r2 >> 2,  j   = r2 & 3;
        int src = g*256 + d*16 + c4*4 + j;
        ws1[idx] = w1[src]; ws2[idx] = w2[src]; ws3[idx] = w3[src];
    }
    __syncthreads();

    int quad = tid & 3;
    int csl  = quad*4;                           // owned channel slice base
    int gid  = blockIdx.x*32 + (tid >> 2);
    int bb = gid / HW, p = gid - bb*HW;
    int y = p / IMGW, x = p - y*IMGW;
    const float* hb = g_h[which] + (size_t)bb*HID*HW;

    float v1r[9][4], v3r[9][4];

    #pragma unroll
    for (int g = 0; g < 9; g++) {
        int yy = y + shift*c_dy[g];
        int xx = x + shift*c_dx[g];
        bool inb = ((unsigned)yy < (unsigned)IMGH) && ((unsigned)xx < (unsigned)IMGW);
        float sgn = (g < 8) ? -1.f : 1.f;
        float hq[4];
        if (inb) {
            const float* hp = hb + yy*IMGW + xx;
            #pragma unroll
            for (int j = 0; j < 4; j++) hq[j] = sgn*__ldg(&hp[(size_t)(csl+j)*HW]);
        } else {
            hq[0]=hq[1]=hq[2]=hq[3]=0.f;
        }
        float hall[16];
        #pragma unroll
        for (int q = 0; q < 4; q++)
            #pragma unroll
            for (int j = 0; j < 4; j++)
                hall[q*4+j] = __shfl_sync(0xffffffffu, hq[j], q, 4);

        #pragma unroll
        for (int dd = 0; dd < 4; dd++) {
            int d = csl + dd;
            float a = 0.f, b = 0.f;
            #pragma unroll
            for (int q4 = 0; q4 < 4; q4++) {
                float4 wa = *(const float4*)&ws1[g*256 + q4*64 + d*4];
                float4 wb = *(const float4*)&ws3[g*256 + q4*64 + d*4];
                a += wa.x*hall[q4*4] + wa.y*hall[q4*4+1] + wa.z*hall[q4*4+2] + wa.w*hall[q4*4+3];
                b += wb.x*hall[q4*4] + wb.y*hall[q4*4+1] + wb.z*hall[q4*4+2] + wb.w*hall[q4*4+3];
            }
            v1r[g][dd] = a; v3r[g][dd] = b;
        }
    }

    float sc = __ldg(&scale[sidx]);
    float* catb = g_cat + (size_t)bb*CCAT*HW + (size_t)cbase*HW + p;

    for (int pp = 0; pp < 9; pp++) {
        int yy = y + shift*c_dy[pp];
        int xx = x + shift*c_dx[pp];
        bool inb = ((unsigned)yy < (unsigned)IMGH) && ((unsigned)xx < (unsigned)IMGW);
        float sgn = (pp < 8) ? -1.f : 1.f;
        float hq[4];
        if (inb) {
            const float* hp = hb + yy*IMGW + xx;
            #pragma unroll
            for (int j = 0; j < 4; j++) hq[j] = sgn*__ldg(&hp[(size_t)(csl+j)*HW]);
        } else {
            hq[0]=hq[1]=hq[2]=hq[3]=0.f;
        }
        float hall[16];
        #pragma unroll
        for (int q = 0; q < 4; q++)
            #pragma unroll
            for (int j = 0; j < 4; j++)
                hall[q*4+j] = __shfl_sync(0xffffffffu, hq[j], q, 4);

        float v2p[4];
        #pragma unroll
        for (int dd = 0; dd < 4; dd++) {
            int d = csl + dd;
            float a = 0.f;
            #pragma unroll
            for (int q4 = 0; q4 < 4; q4++) {
                float4 wv = *(const float4*)&ws2[pp*256 + q4*64 + d*4];
                a += wv.x*hall[q4*4] + wv.y*hall[q4*4+1] + wv.z*hall[q4*4+2] + wv.w*hall[q4*4+3];
            }
            v2p[dd] = a;
        }

        float lg[9];
        #pragma unroll
        for (int q = 0; q < 9; q++) {
            float l = v2p[0]*v1r[q][0] + v2p[1]*v1r[q][1]
                    + v2p[2]*v1r[q][2] + v2p[3]*v1r[q][3];
            l += __shfl_xor_sync(0xffffffffu, l, 1, 4);
            l += __shfl_xor_sync(0xffffffffu, l, 2, 4);
            lg[q] = l * sc;
        }
        float m = lg[0];
        #pragma unroll
        for (int q = 1; q < 9; q++) m = fmaxf(m, lg[q]);
        float s = 0.f;
        #pragma unroll
        for (int q = 0; q < 9; q++) { lg[q] = __expf(lg[q] - m); s += lg[q]; }
        float inv = 1.f / s;

        float oa[4] = {0.f, 0.f, 0.f, 0.f};
        #pragma unroll
        for (int q = 0; q < 9; q++) {
            float a = lg[q] * inv;
            oa[0] += a*v3r[q][0]; oa[1] += a*v3r[q][1];
            oa[2] += a*v3r[q][2]; oa[3] += a*v3r[q][3];
        }
        #pragma unroll
        for (int dd = 0; dd < 4; dd++)
            catb[(size_t)(pp*16 + csl + dd)*HW] = oa[dd];
    }
}

// ---------------- K5: final 1x1 conv 288->128 (+bias), f32x2 -------------
// 2 pixels/thread (p, p+256); o split in halves across blockIdx.y;
// weight pairs (o,o+1) via LDS.64 from o-contiguous smem.
__global__ void __launch_bounds__(256)
k_out(const float* __restrict__ wo, const float* __restrict__ bo,
      float* __restrict__ out)
{
    extern __shared__ float ws[];                // [288][66], o-contiguous
    int tid = threadIdx.x;
    int obase = blockIdx.y*64;
    for (int j = tid; j < 288*64; j += 256) {
        int o = j / 288, i = j - o*288;          // i fast -> coalesced global
        ws[i*66 + o] = __ldg(&wo[(size_t)(obase+o)*CCAT + i]);
    }
    __syncthreads();

    int g0 = blockIdx.x*512 + tid;
    int bb = g0 / HW;
    int p0 = g0 - bb*HW;
    const float* cp0 = g_cat + (size_t)bb*CCAT*HW + p0;
    const float* cp1 = cp0 + 256;

    unsigned long long acc0[32], acc1[32];
    #pragma unroll
    for (int op = 0; op < 32; op++) { acc0[op] = 0ull; acc1[op] = 0ull; }

    #pragma unroll 4
    for (int i = 0; i < CCAT; i++) {
        float v0 = __ldg(&cp0[(size_t)i*HW]);
        float v1 = __ldg(&cp1[(size_t)i*HW]);
        unsigned long long xv0, xv1;
        PACK2(xv0, v0, v0);
        PACK2(xv1, v1, v1);
        const unsigned long long* wp = (const unsigned long long*)&ws[i*66];
        #pragma unroll
        for (int op = 0; op < 32; op++) {
            unsigned long long wv = wp[op];
            FMA2(acc0[op], wv, xv0);
            FMA2(acc1[op], wv, xv1);
        }
    }

    float* ob = out + (size_t)bb*COUT*HW + p0;
    #pragma unroll
    for (int op = 0; op < 32; op++) {
        float a0,a1,b0,b1;
        UNPACK2(a0, a1, acc0[op]);
        UNPACK2(b0, b1, acc1[op]);
        float bv0 = __ldg(&bo[obase + 2*op]);
        float bv1 = __ldg(&bo[obase + 2*op + 1]);
        ob[(size_t)(obase + 2*op    )*HW]       = a0 + bv0;
        ob[(size_t)(obase + 2*op + 1)*HW]       = a1 + bv1;
        ob[(size_t)(obase + 2*op    )*HW + 256] = b0 + bv0;
        ob[(size_t)(obase + 2*op + 1)*HW + 256] = b1 + bv1;
    }
}

// ---------------- launcher ----------------
extern "C" void kernel_launch(void* const* d_in, const int* in_sizes, int n_in,
                              void* d_out, int out_size)
{
    const float* cen   = (const float*)d_in[0];
    const float* in_w0 = (const float*)d_in[1];
    const float* in_b0 = (const float*)d_in[2];
    const float* in_w1 = (const float*)d_in[3];
    const float* in_b1 = (const float*)d_in[4];
    const float* w1_0  = (const float*)d_in[5];
    const float* w2_0  = (const float*)d_in[6];
    const float* w3_0  = (const float*)d_in[7];
    const float* w1_1  = (const float*)d_in[8];
    const float* w2_1  = (const float*)d_in[9];
    const float* w3_1  = (const float*)d_in[10];
    const float* scale = (const float*)d_in[11];
    const float* out_w = (const float*)d_in[12];
    const float* out_b = (const float*)d_in[13];
    float* out = (float*)d_out;

    size_t out_smem = (size_t)288*66*sizeof(float);      // 76032 B
    cudaFuncSetAttribute(k_out, cudaFuncAttributeMaxDynamicSharedMemorySize,
                         (int)out_smem);

    k_prep<<<(CIN*288 + 255)/256, 256>>>(in_w1);
    k_conv1x1<<<HB*HW/256, 256>>>(cen, in_w0, in_b0);
    k_conv3x3<<<dim3(IMGW/64, IMGH/16, HB), dim3(16, 16)>>>(cen, in_b1);
    k_branch<<<HB*HW/32, 128>>>(0, w1_0, w2_0, w3_0, scale, 0, 1, 0);
    k_branch<<<HB*HW/32, 128>>>(1, w1_1, w2_1, w3_1, scale, 1, 5, 144);
    k_out<<<dim3(HB*HW/512, 2), 256, out_smem>>>(out_w, out_b, out);
}

// round 3
// speedup vs baseline: 1.1991x; 1.1991x over previous
#include <cuda_runtime.h>
#include <cstdint>

#define HB   4
#define CIN  256
#define HID  16
#define IMGH 192
#define IMGW 192
#define HW   (IMGH*IMGW)        // 36864
#define COUT 128
#define CCAT 288

typedef unsigned long long ull;
#define FMA2(acc,a,b)  asm("fma.rn.f32x2 %0, %1, %2, %0;" : "+l"(acc) : "l"(a), "l"(b))
#define PACK2(d,lo,hi) asm("mov.b64 %0, {%1, %2};" : "=l"(d) : "f"(lo), "f"(hi))
#define UNPACK2(lo,hi,s) asm("mov.b64 {%0, %1}, %2;" : "=f"(lo), "=f"(hi) : "l"(s))

// ---------------- scratch (device globals; no allocation) ----------------
__device__ float g_h[2][HB*HID*HW];        // h0, h1
__device__ float g_cat[HB*CCAT*HW];        // branch outputs concatenated
__device__ float g_w2p[CIN*288];           // 3x3 weights: [ci][o][t][dup2]

__constant__ int c_dy[9] = {-1,-1,-1, 0, 1, 1, 1, 0, 0};
__constant__ int c_dx[9] = {-1, 0, 1, 1, 1, 0,-1,-1, 0};

// ---------------- prep: repack 3x3 weights, duplicated pairs --------------
__global__ void k_prep(const float* __restrict__ w)
{
    int idx = blockIdx.x*256 + threadIdx.x;      // 0 .. 256*288
    if (idx >= CIN*288) return;
    int rem = idx % 288;
    int ci  = idx / 288;
    int o   = rem / 18;
    int t   = (rem % 18) >> 1;
    g_w2p[idx] = w[(o*CIN + ci)*9 + t];          // in_w1[o][ci][ky][kx], dup 2x
}

// ---------------- K1: 1x1 conv 256->16 (+bias) -> g_h[0], f32x2 ---------
__global__ void __launch_bounds__(256)
k_conv1x1(const float* __restrict__ cen,
          const float* __restrict__ w,
          const float* __restrict__ bias)
{
    __shared__ float ws[CIN*16];                 // ws[i][o]
    int tid = threadIdx.x;
    for (int j = tid; j < CIN*16; j += 256) {
        int o = j >> 8, i = j & 255;
        ws[i*16 + o] = w[j];
    }
    __syncthreads();

    int gid = blockIdx.x*256 + tid;
    int bb = gid / HW, p = gid - bb*HW;
    const float* cp = cen + (size_t)bb*CIN*HW + p;

    ull acc[8];
    #pragma unroll
    for (int k = 0; k < 8; k++)
        PACK2(acc[k], __ldg(&bias[2*k]), __ldg(&bias[2*k+1]));

    float v = __ldg(&cp[0]);
    #pragma unroll 4
    for (int i = 0; i < CIN; i++) {
        float vn = (i < CIN-1) ? __ldg(&cp[(size_t)(i+1)*HW]) : 0.f;
        ull xp; PACK2(xp, v, v);
        const ull* wp = (const ull*)&ws[i*16];
        #pragma unroll
        for (int k = 0; k < 8; k++) { ull wv = wp[k]; FMA2(acc[k], wv, xp); }
        v = vn;
    }
    float* hp = g_h[0] + (size_t)bb*HID*HW + p;
    #pragma unroll
    for (int k = 0; k < 8; k++) {
        float a0, a1;
        UNPACK2(a0, a1, acc[k]);
        hp[(size_t)(2*k  )*HW] = a0;
        hp[(size_t)(2*k+1)*HW] = a1;
    }
}

// ---------------- K2: 3x3 conv 256->16 (+bias), double-buffered ----------
// block (16,16); tile 64x16 px; 4 px/thread; 1 sync per ci; reg prefetch.
__global__ void __launch_bounds__(256)
k_conv3x3(const float* __restrict__ cen,
          const float* __restrict__ bias)
{
    __shared__ float tile[2][18][68];            // (16+2) x (64+2) pad->68
    __shared__ float wch[2][288];
    int tx = threadIdx.x, ty = threadIdx.y;
    int tid = ty*16 + tx;
    int x0 = blockIdx.x*64 - 1;
    int y0 = blockIdx.y*16 - 1;
    int bz = blockIdx.z;
    const float* cb = cen + (size_t)bz*CIN*HW;

    // precompute per-thread load slots (constant across ci)
    int gofs[5], smofs[5];
    bool vld[5], act[5];
    #pragma unroll
    for (int k = 0; k < 5; k++) {
        int j = tid + k*256;
        act[k] = (j < 18*66);
        int r = j / 66, c = j - r*66;
        int gy = y0 + r, gx = x0 + c;
        vld[k] = act[k] && ((unsigned)gy < (unsigned)IMGH) && ((unsigned)gx < (unsigned)IMGW);
        gofs[k]  = gy*IMGW + gx;
        smofs[k] = r*68 + c;
    }

    ull accA[16], accB[16];
    #pragma unroll
    for (int o = 0; o < 16; o++) { accA[o] = 0ull; accB[o] = 0ull; }

    float pf[5], wpf[2];
    // prologue: load ci=0
    {
        const float* cc = cb;
        #pragma unroll
        for (int k = 0; k < 5; k++) pf[k] = vld[k] ? __ldg(&cc[gofs[k]]) : 0.f;
        #pragma unroll
        for (int k = 0; k < 2; k++) { int j = tid + k*256; wpf[k] = (j < 288) ? g_w2p[j] : 0.f; }
        float* tb = &tile[0][0][0];
        #pragma unroll
        for (int k = 0; k < 5; k++) if (act[k]) tb[smofs[k]] = pf[k];
        #pragma unroll
        for (int k = 0; k < 2; k++) { int j = tid + k*256; if (j < 288) wch[0][j] = wpf[k]; }
    }

    for (int ci = 0; ci < CIN; ci++) {
        __syncthreads();
        int cur = ci & 1;
        if (ci < CIN-1) {
            const float* cc = cb + (size_t)(ci+1)*HW;
            #pragma unroll
            for (int k = 0; k < 5; k++) pf[k] = vld[k] ? __ldg(&cc[gofs[k]]) : 0.f;
            #pragma unroll
            for (int k = 0; k < 2; k++) { int j = tid + k*256; wpf[k] = (j < 288) ? g_w2p[(size_t)(ci+1)*288 + j] : 0.f; }
        }

        ull pr[3][5];
        #pragma unroll
        for (int r = 0; r < 3; r++) {
            const float* trp = &tile[cur][ty+r][4*tx];
            float4 f  = *(const float4*)trp;
            float2 g2 = *(const float2*)(trp + 4);
            PACK2(pr[r][0], f.x, f.y);
            PACK2(pr[r][1], f.y, f.z);
            PACK2(pr[r][2], f.z, f.w);
            PACK2(pr[r][3], f.w, g2.x);
            PACK2(pr[r][4], g2.x, g2.y);
        }
        #pragma unroll
        for (int o = 0; o < 16; o++) {
            const ull* wp = (const ull*)&wch[cur][o*18];
            #pragma unroll
            for (int r = 0; r < 3; r++) {
                #pragma unroll
                for (int k = 0; k < 3; k++) {
                    ull wv = wp[r*3+k];
                    FMA2(accA[o], wv, pr[r][k]);
                    FMA2(accB[o], wv, pr[r][k+2]);
                }
            }
        }

        if (ci < CIN-1) {
            float* tb = &tile[cur^1][0][0];
            #pragma unroll
            for (int k = 0; k < 5; k++) if (act[k]) tb[smofs[k]] = pf[k];
            #pragma unroll
            for (int k = 0; k < 2; k++) { int j = tid + k*256; if (j < 288) wch[cur^1][j] = wpf[k]; }
        }
    }

    int gx = blockIdx.x*64 + 4*tx;
    int gy = y0 + 1 + ty;
    float* hp = g_h[1] + (size_t)bz*HID*HW + gy*IMGW + gx;
    #pragma unroll
    for (int o = 0; o < 16; o++) {
        float a0,a1,a2,a3;
        UNPACK2(a0, a1, accA[o]);
        UNPACK2(a2, a3, accB[o]);
        float bv = __ldg(&bias[o]);
        *(float4*)&hp[(size_t)o*HW] = make_float4(a0+bv, a1+bv, a2+bv, a3+bv);
    }
}

// ---------------- K3/K4: branch (shift attention), v1->attn->v3 ----------
// 128 thr, 1 px/thread. Phase 1: v1 -> private smem. Phase 2: attn rows ->
// 81 regs. Phase 3: v3 overwrites same smem. Phase 4: apply. One phased
// weight buffer (9.2KB). smem = 85KB -> 2 CTAs/SM.
#define PADV 148
__global__ void __launch_bounds__(128)
k_branch(int which,
         const float* __restrict__ w1, const float* __restrict__ w2,
         const float* __restrict__ w3, const float* __restrict__ scale,
         int sidx, int shift, int cbase)
{
    extern __shared__ float sm[];
    float* wbuf = sm;                 // 2304
    float* sv   = sm + 2304;          // 128 * PADV

    int tid = threadIdx.x;
    for (int j = tid; j < 2304; j += 128) wbuf[j] = w1[j];
    __syncthreads();

    int gid = blockIdx.x*128 + tid;
    int bb = gid / HW, p = gid - bb*HW;
    int y = p / IMGW, x = p - y*IMGW;
    const float* hb = g_h[which] + (size_t)bb*HID*HW;
    float* svt = sv + tid*PADV;

    float hv[16];

    // ---- Phase 1: v1[g] -> private smem ----
    #pragma unroll 1
    for (int g = 0; g < 9; g++) {
        int yy = y + shift*c_dy[g];
        int xx = x + shift*c_dx[g];
        bool inb = ((unsigned)yy < (unsigned)IMGH) && ((unsigned)xx < (unsigned)IMGW);
        float sgn = (g < 8) ? -1.f : 1.f;
        const float* hp = hb + yy*IMGW + xx;
        #pragma unroll
        for (int c = 0; c < 16; c++)
            hv[c] = inb ? sgn*__ldg(&hp[(size_t)c*HW]) : 0.f;

        const float* wg = wbuf + g*256;
        #pragma unroll
        for (int d4 = 0; d4 < 4; d4++) {
            float t[4];
            #pragma unroll
            for (int dd = 0; dd < 4; dd++) {
                const float4* wr = (const float4*)(wg + (d4*4+dd)*16);
                float a = 0.f;
                #pragma unroll
                for (int q4 = 0; q4 < 4; q4++) {
                    float4 wv = wr[q4];
                    a += wv.x*hv[q4*4] + wv.y*hv[q4*4+1] + wv.z*hv[q4*4+2] + wv.w*hv[q4*4+3];
                }
                t[dd] = a;
            }
            *(float4*)&svt[g*16 + d4*4] = make_float4(t[0],t[1],t[2],t[3]);
        }
    }
    __syncthreads();
    for (int j = tid; j < 2304; j += 128) wbuf[j] = w2[j];
    __syncthreads();

    float sc = __ldg(&scale[sidx]);

    // ---- Phase 2: attention rows (normalized) -> 81 regs ----
    float att[81];
    #pragma unroll
    for (int pp = 0; pp < 9; pp++) {
        int yy = y + shift*c_dy[pp];
        int xx = x + shift*c_dx[pp];
        bool inb = ((unsigned)yy < (unsigned)IMGH) && ((unsigned)xx < (unsigned)IMGW);
        float sgn = (pp < 8) ? -1.f : 1.f;
        const float* hp = hb + yy*IMGW + xx;
        #pragma unroll
        for (int c = 0; c < 16; c++)
            hv[c] = inb ? sgn*__ldg(&hp[(size_t)c*HW]) : 0.f;

        float v2[16];
        const float* wg = wbuf + pp*256;
        #pragma unroll
        for (int d = 0; d < 16; d++) {
            const float4* wr = (const float4*)(wg + d*16);
            float a = 0.f;
            #pragma unroll
            for (int q4 = 0; q4 < 4; q4++) {
                float4 wv = wr[q4];
                a += wv.x*hv[q4*4] + wv.y*hv[q4*4+1] + wv.z*hv[q4*4+2] + wv.w*hv[q4*4+3];
            }
            v2[d] = a;
        }

        float lg[9];
        #pragma unroll
        for (int q = 0; q < 9; q++) {
            const float4* u = (const float4*)&svt[q*16];
            float4 u0 = u[0], u1 = u[1], u2 = u[2], u3 = u[3];
            float a = u0.x*v2[0]  + u0.y*v2[1]  + u0.z*v2[2]  + u0.w*v2[3]
                    + u1.x*v2[4]  + u1.y*v2[5]  + u1.z*v2[6]  + u1.w*v2[7]
                    + u2.x*v2[8]  + u2.y*v2[9]  + u2.z*v2[10] + u2.w*v2[11]
                    + u3.x*v2[12] + u3.y*v2[13] + u3.z*v2[14] + u3.w*v2[15];
            lg[q] = a * sc;
        }
        float m = lg[0];
        #pragma unroll
        for (int q = 1; q < 9; q++) m = fmaxf(m, lg[q]);
        float s = 0.f;
        #pragma unroll
        for (int q = 0; q < 9; q++) { lg[q] = __expf(lg[q] - m); s += lg[q]; }
        float inv = 1.f / s;
        #pragma unroll
        for (int q = 0; q < 9; q++) att[pp*9+q] = lg[q] * inv;
    }
    __syncthreads();
    for (int j = tid; j < 2304; j += 128) wbuf[j] = w3[j];
    __syncthreads();

    // ---- Phase 3: v3[g] overwrites private smem (thread-private, no sync) ----
    #pragma unroll 1
    for (int g = 0; g < 9; g++) {
        int yy = y + shift*c_dy[g];
        int xx = x + shift*c_dx[g];
        bool inb = ((unsigned)yy < (unsigned)IMGH) && ((unsigned)xx < (unsigned)IMGW);
        float sgn = (g < 8) ? -1.f : 1.f;
        const float* hp = hb + yy*IMGW + xx;
        #pragma unroll
        for (int c = 0; c < 16; c++)
            hv[c] = inb ? sgn*__ldg(&hp[(size_t)c*HW]) : 0.f;

        const float* wg = wbuf + g*256;
        #pragma unroll
        for (int d4 = 0; d4 < 4; d4++) {
            float t[4];
            #pragma unroll
            for (int dd = 0; dd < 4; dd++) {
                const float4* wr = (const float4*)(wg + (d4*4+dd)*16);
                float a = 0.f;
                #pragma unroll
                for (int q4 = 0; q4 < 4; q4++) {
                    float4 wv = wr[q4];
                    a += wv.x*hv[q4*4] + wv.y*hv[q4*4+1] + wv.z*hv[q4*4+2] + wv.w*hv[q4*4+3];
                }
                t[dd] = a;
            }
            *(float4*)&svt[g*16 + d4*4] = make_float4(t[0],t[1],t[2],t[3]);
        }
    }

    // ---- Phase 4: out[p] = sum_q att[p][q] * v3[q] ----
    float* catb = g_cat + (size_t)bb*CCAT*HW + (size_t)cbase*HW + p;
    #pragma unroll
    for (int pp = 0; pp < 9; pp++) {
        float oa[16];
        #pragma unroll
        for (int c = 0; c < 16; c++) oa[c] = 0.f;
        #pragma unroll
        for (int q = 0; q < 9; q++) {
            float a = att[pp*9+q];
            const float4* u = (const float4*)&svt[q*16];
            float4 u0 = u[0], u1 = u[1], u2 = u[2], u3 = u[3];
            oa[0]  += a*u0.x; oa[1]  += a*u0.y; oa[2]  += a*u0.z; oa[3]  += a*u0.w;
            oa[4]  += a*u1.x; oa[5]  += a*u1.y; oa[6]  += a*u1.z; oa[7]  += a*u1.w;
            oa[8]  += a*u2.x; oa[9]  += a*u2.y; oa[10] += a*u2.z; oa[11] += a*u2.w;
            oa[12] += a*u3.x; oa[13] += a*u3.y; oa[14] += a*u3.z; oa[15] += a*u3.w;
        }
        #pragma unroll
        for (int c = 0; c < 16; c++)
            catb[(size_t)(pp*16 + c)*HW] = oa[c];
    }
}

// ---------------- K5: final 1x1 conv 288->128, register-tiled ------------
// 256 thr; thread tile 4px x 16outs (8 FFMA2 pairs); block tile 128px x 128o.
// All weights resident in smem [i][o] (row 132), broadcast LDS.64 reads.
__global__ void __launch_bounds__(256)
k_out(const float* __restrict__ wo, const float* __restrict__ bo,
      float* __restrict__ out)
{
    extern __shared__ float ws[];                // [288][132]
    int tid = threadIdx.x;
    for (int j = tid; j < 288*128; j += 256) {
        int o = j / 288, i = j - o*288;          // j = o*288+i -> coalesced LDG
        ws[i*132 + o] = __ldg(&wo[j]);
    }
    __syncthreads();

    int out_t = tid >> 5;                        // 0..7 -> o0 = 16*out_t
    int px_t  = tid & 31;                        // 0..31 -> 4 px each
    int o0 = out_t*16;
    int gpx = blockIdx.x*128 + px_t*4;
    int bb = gpx / HW, p0 = gpx - bb*HW;
    const float* cp = g_cat + (size_t)bb*CCAT*HW + p0;

    ull acc[4][8];
    #pragma unroll
    for (int px = 0; px < 4; px++)
        #pragma unroll
        for (int pr = 0; pr < 8; pr++) acc[px][pr] = 0ull;

    float4 xv = __ldg((const float4*)cp);
    #pragma unroll 2
    for (int i = 0; i < CCAT; i++) {
        float4 xn = make_float4(0.f,0.f,0.f,0.f);
        if (i < CCAT-1) xn = __ldg((const float4*)(cp + (size_t)(i+1)*HW));
        ull xp[4];
        PACK2(xp[0], xv.x, xv.x);
        PACK2(xp[1], xv.y, xv.y);
        PACK2(xp[2], xv.z, xv.z);
        PACK2(xp[3], xv.w, xv.w);
        const ull* wp = (const ull*)&ws[i*132 + o0];
        #pragma unroll
        for (int pr = 0; pr < 8; pr++) {
            ull wv = wp[pr];
            FMA2(acc[0][pr], wv, xp[0]);
            FMA2(acc[1][pr], wv, xp[1]);
            FMA2(acc[2][pr], wv, xp[2]);
            FMA2(acc[3][pr], wv, xp[3]);
        }
        xv = xn;
    }

    float* ob = out + (size_t)bb*COUT*HW + p0;
    #pragma unroll
    for (int pr = 0; pr < 8; pr++) {
        float lo[4], hi[4];
        #pragma unroll
        for (int px = 0; px < 4; px++) UNPACK2(lo[px], hi[px], acc[px][pr]);
        float bv0 = __ldg(&bo[o0 + 2*pr]);
        float bv1 = __ldg(&bo[o0 + 2*pr + 1]);
        *(float4*)&ob[(size_t)(o0 + 2*pr    )*HW] =
            make_float4(lo[0]+bv0, lo[1]+bv0, lo[2]+bv0, lo[3]+bv0);
        *(float4*)&ob[(size_t)(o0 + 2*pr + 1)*HW] =
            make_float4(hi[0]+bv1, hi[1]+bv1, hi[2]+bv1, hi[3]+bv1);
    }
}

// ---------------- launcher ----------------
extern "C" void kernel_launch(void* const* d_in, const int* in_sizes, int n_in,
                              void* d_out, int out_size)
{
    const float* cen   = (const float*)d_in[0];
    const float* in_w0 = (const float*)d_in[1];
    const float* in_b0 = (const float*)d_in[2];
    const float* in_w1 = (const float*)d_in[3];
    const float* in_b1 = (const float*)d_in[4];
    const float* w1_0  = (const float*)d_in[5];
    const float* w2_0  = (const float*)d_in[6];
    const float* w3_0  = (const float*)d_in[7];
    const float* w1_1  = (const float*)d_in[8];
    const float* w2_1  = (const float*)d_in[9];
    const float* w3_1  = (const float*)d_in[10];
    const float* scale = (const float*)d_in[11];
    const float* out_w = (const float*)d_in[12];
    const float* out_b = (const float*)d_in[13];
    float* out = (float*)d_out;

    size_t br_smem  = (size_t)(2304 + 128*PADV)*sizeof(float);   // 84992 B
    size_t out_smem = (size_t)288*132*sizeof(float);             // 152064 B
    cudaFuncSetAttribute(k_branch, cudaFuncAttributeMaxDynamicSharedMemorySize,
                         (int)br_smem);
    cudaFuncSetAttribute(k_out, cudaFuncAttributeMaxDynamicSharedMemorySize,
                         (int)out_smem);

    k_prep<<<(CIN*288)/256, 256>>>(in_w1);
    k_conv1x1<<<HB*HW/256, 256>>>(cen, in_w0, in_b0);
    k_conv3x3<<<dim3(IMGW/64, IMGH/16, HB), dim3(16, 16)>>>(cen, in_b1);
    k_branch<<<HB*HW/128, 128, br_smem>>>(0, w1_0, w2_0, w3_0, scale, 0, 1, 0);
    k_branch<<<HB*HW/128, 128, br_smem>>>(1, w1_1, w2_1, w3_1, scale, 1, 5, 144);
    k_out<<<HB*HW/128, 256, out_smem>>>(out_w, out_b, out);
}

// round 4
// speedup vs baseline: 1.5444x; 1.2880x over previous
#include <cuda_runtime.h>
#include <cstdint>

#define HB   4
#define CIN  256
#define HID  16
#define IMGH 192
#define IMGW 192
#define HW   (IMGH*IMGW)        // 36864
#define COUT 128
#define CCAT 288

typedef unsigned long long ull;
#define FMA2(acc,a,b)  asm("fma.rn.f32x2 %0, %1, %2, %0;" : "+l"(acc) : "l"(a), "l"(b))
#define PACK2(d,lo,hi) asm("mov.b64 %0, {%1, %2};" : "=l"(d) : "f"(lo), "f"(hi))
#define UNPACK2(lo,hi,s) asm("mov.b64 {%0, %1}, %2;" : "=f"(lo), "=f"(hi) : "l"(s))

// ---------------- scratch (device globals; no allocation) ----------------
__device__ float g_h[2][HB*HID*HW];        // h0, h1
__device__ float g_cat[HB*CCAT*HW];        // branch outputs concatenated
__device__ float g_w2p[CIN*288];           // 3x3 weights: [ci][o][t][dup2]

__constant__ int c_dy[9] = {-1,-1,-1, 0, 1, 1, 1, 0, 0};
__constant__ int c_dx[9] = {-1, 0, 1, 1, 1, 0,-1,-1, 0};

// ---------------- prep: repack 3x3 weights, duplicated pairs --------------
__global__ void k_prep(const float* __restrict__ w)
{
    int idx = blockIdx.x*256 + threadIdx.x;      // 0 .. 256*288
    if (idx >= CIN*288) return;
    int rem = idx % 288;
    int ci  = idx / 288;
    int o   = rem / 18;
    int t   = (rem % 18) >> 1;
    g_w2p[idx] = w[(o*CIN + ci)*9 + t];          // in_w1[o][ci][ky][kx], dup 2x
}

// ---------------- K1: 1x1 conv 256->16 (+bias), 4-deep prefetch ----------
__global__ void __launch_bounds__(256)
k_conv1x1(const float* __restrict__ cen,
          const float* __restrict__ w,
          const float* __restrict__ bias)
{
    __shared__ float ws[CIN*16];                 // ws[i][o]
    int tid = threadIdx.x;
    for (int j = tid; j < CIN*16; j += 256) {
        int o = j >> 8, i = j & 255;
        ws[i*16 + o] = w[j];
    }
    __syncthreads();

    int gid = blockIdx.x*256 + tid;
    int bb = gid / HW, p = gid - bb*HW;
    const float* cp = cen + (size_t)bb*CIN*HW + p;

    ull acc[8];
    #pragma unroll
    for (int k = 0; k < 8; k++)
        PACK2(acc[k], __ldg(&bias[2*k]), __ldg(&bias[2*k+1]));

    float xr[4];
    #pragma unroll
    for (int d = 0; d < 4; d++) xr[d] = __ldg(&cp[(size_t)d*HW]);

    for (int i0 = 0; i0 < CIN; i0 += 4) {
        #pragma unroll
        for (int u = 0; u < 4; u++) {
            float v = xr[u];
            if (i0 + u + 4 < CIN) xr[u] = __ldg(&cp[(size_t)(i0+u+4)*HW]);
            ull xp; PACK2(xp, v, v);
            const ull* wp = (const ull*)&ws[(i0+u)*16];
            #pragma unroll
            for (int k = 0; k < 8; k++) { ull wv = wp[k]; FMA2(acc[k], wv, xp); }
        }
    }
    float* hp = g_h[0] + (size_t)bb*HID*HW + p;
    #pragma unroll
    for (int k = 0; k < 8; k++) {
        float a0, a1;
        UNPACK2(a0, a1, acc[k]);
        hp[(size_t)(2*k  )*HW] = a0;
        hp[(size_t)(2*k+1)*HW] = a1;
    }
}

// ---------------- K2: 3x3 conv 256->16 (+bias), double-buffered ----------
__global__ void __launch_bounds__(256)
k_conv3x3(const float* __restrict__ cen,
          const float* __restrict__ bias)
{
    __shared__ float tile[2][18][68];
    __shared__ float wch[2][288];
    int tx = threadIdx.x, ty = threadIdx.y;
    int tid = ty*16 + tx;
    int x0 = blockIdx.x*64 - 1;
    int y0 = blockIdx.y*16 - 1;
    int bz = blockIdx.z;
    const float* cb = cen + (size_t)bz*CIN*HW;

    int gofs[5], smofs[5];
    bool vld[5], act[5];
    #pragma unroll
    for (int k = 0; k < 5; k++) {
        int j = tid + k*256;
        act[k] = (j < 18*66);
        int r = j / 66, c = j - r*66;
        int gy = y0 + r, gx = x0 + c;
        vld[k] = act[k] && ((unsigned)gy < (unsigned)IMGH) && ((unsigned)gx < (unsigned)IMGW);
        gofs[k]  = gy*IMGW + gx;
        smofs[k] = r*68 + c;
    }

    ull accA[16], accB[16];
    #pragma unroll
    for (int o = 0; o < 16; o++) { accA[o] = 0ull; accB[o] = 0ull; }

    float pf[5], wpf[2];
    {
        const float* cc = cb;
        #pragma unroll
        for (int k = 0; k < 5; k++) pf[k] = vld[k] ? __ldg(&cc[gofs[k]]) : 0.f;
        #pragma unroll
        for (int k = 0; k < 2; k++) { int j = tid + k*256; wpf[k] = (j < 288) ? g_w2p[j] : 0.f; }
        float* tb = &tile[0][0][0];
        #pragma unroll
        for (int k = 0; k < 5; k++) if (act[k]) tb[smofs[k]] = pf[k];
        #pragma unroll
        for (int k = 0; k < 2; k++) { int j = tid + k*256; if (j < 288) wch[0][j] = wpf[k]; }
    }

    for (int ci = 0; ci < CIN; ci++) {
        __syncthreads();
        int cur = ci & 1;
        if (ci < CIN-1) {
            const float* cc = cb + (size_t)(ci+1)*HW;
            #pragma unroll
            for (int k = 0; k < 5; k++) pf[k] = vld[k] ? __ldg(&cc[gofs[k]]) : 0.f;
            #pragma unroll
            for (int k = 0; k < 2; k++) { int j = tid + k*256; wpf[k] = (j < 288) ? g_w2p[(size_t)(ci+1)*288 + j] : 0.f; }
        }

        ull pr[3][5];
        #pragma unroll
        for (int r = 0; r < 3; r++) {
            const float* trp = &tile[cur][ty+r][4*tx];
            float4 f  = *(const float4*)trp;
            float2 g2 = *(const float2*)(trp + 4);
            PACK2(pr[r][0], f.x, f.y);
            PACK2(pr[r][1], f.y, f.z);
            PACK2(pr[r][2], f.z, f.w);
            PACK2(pr[r][3], f.w, g2.x);
            PACK2(pr[r][4], g2.x, g2.y);
        }
        #pragma unroll
        for (int o = 0; o < 16; o++) {
            const ull* wp = (const ull*)&wch[cur][o*18];
            #pragma unroll
            for (int r = 0; r < 3; r++) {
                #pragma unroll
                for (int k = 0; k < 3; k++) {
                    ull wv = wp[r*3+k];
                    FMA2(accA[o], wv, pr[r][k]);
                    FMA2(accB[o], wv, pr[r][k+2]);
                }
            }
        }

        if (ci < CIN-1) {
            float* tb = &tile[cur^1][0][0];
            #pragma unroll
            for (int k = 0; k < 5; k++) if (act[k]) tb[smofs[k]] = pf[k];
            #pragma unroll
            for (int k = 0; k < 2; k++) { int j = tid + k*256; if (j < 288) wch[cur^1][j] = wpf[k]; }
        }
    }

    int gx = blockIdx.x*64 + 4*tx;
    int gy = y0 + 1 + ty;
    float* hp = g_h[1] + (size_t)bz*HID*HW + gy*IMGW + gx;
    #pragma unroll
    for (int o = 0; o < 16; o++) {
        float a0,a1,a2,a3;
        UNPACK2(a0, a1, accA[o]);
        UNPACK2(a2, a3, accB[o]);
        float bv = __ldg(&bias[o]);
        *(float4*)&hp[(size_t)o*HW] = make_float4(a0+bv, a1+bv, a2+bv, a3+bv);
    }
}

// ---------------- K3/K4: branch. 96 thr/CTA; v1 + att both in smem -------
// smem = 2304 (weights, phased) + 96*148 (v1/v3) + 96*83 (att) = 97.9KB
// -> 2 CTAs/SM, no register spills.
#define PADV 148
#define PADA 83
#define BTH  96
__global__ void __launch_bounds__(BTH)
k_branch(int which,
         const float* __restrict__ w1, const float* __restrict__ w2,
         const float* __restrict__ w3, const float* __restrict__ scale,
         int sidx, int shift, int cbase)
{
    extern __shared__ float sm[];
    float* wbuf = sm;                    // 2304
    float* sv   = sm + 2304;             // BTH * PADV
    float* atm  = sm + 2304 + BTH*PADV;  // BTH * PADA

    int tid = threadIdx.x;
    for (int j = tid; j < 2304; j += BTH) wbuf[j] = w1[j];
    __syncthreads();

    int gid = blockIdx.x*BTH + tid;
    int bb = gid / HW, p = gid - bb*HW;
    int y = p / IMGW, x = p - y*IMGW;
    const float* hb = g_h[which] + (size_t)bb*HID*HW;
    float* svt = sv + tid*PADV;
    float* att = atm + tid*PADA;

    float hv[16];

    // ---- Phase 1: v1[g] -> private smem ----
    #pragma unroll 1
    for (int g = 0; g < 9; g++) {
        int yy = y + shift*c_dy[g];
        int xx = x + shift*c_dx[g];
        bool inb = ((unsigned)yy < (unsigned)IMGH) && ((unsigned)xx < (unsigned)IMGW);
        float sgn = (g < 8) ? -1.f : 1.f;
        const float* hp = hb + yy*IMGW + xx;
        #pragma unroll
        for (int c = 0; c < 16; c++)
            hv[c] = inb ? sgn*__ldg(&hp[(size_t)c*HW]) : 0.f;

        const float* wg = wbuf + g*256;
        #pragma unroll
        for (int d4 = 0; d4 < 4; d4++) {
            float t[4];
            #pragma unroll
            for (int dd = 0; dd < 4; dd++) {
                const float4* wr = (const float4*)(wg + (d4*4+dd)*16);
                float a = 0.f;
                #pragma unroll
                for (int q4 = 0; q4 < 4; q4++) {
                    float4 wv = wr[q4];
                    a += wv.x*hv[q4*4] + wv.y*hv[q4*4+1] + wv.z*hv[q4*4+2] + wv.w*hv[q4*4+3];
                }
                t[dd] = a;
            }
            *(float4*)&svt[g*16 + d4*4] = make_float4(t[0],t[1],t[2],t[3]);
        }
    }
    __syncthreads();
    for (int j = tid; j < 2304; j += BTH) wbuf[j] = w2[j];
    __syncthreads();

    float sc = __ldg(&scale[sidx]);

    // ---- Phase 2: attention rows (normalized) -> att smem ----
    #pragma unroll 1
    for (int pp = 0; pp < 9; pp++) {
        int yy = y + shift*c_dy[pp];
        int xx = x + shift*c_dx[pp];
        bool inb = ((unsigned)yy < (unsigned)IMGH) && ((unsigned)xx < (unsigned)IMGW);
        float sgn = (pp < 8) ? -1.f : 1.f;
        const float* hp = hb + yy*IMGW + xx;
        #pragma unroll
        for (int c = 0; c < 16; c++)
            hv[c] = inb ? sgn*__ldg(&hp[(size_t)c*HW]) : 0.f;

        float v2[16];
        const float* wg = wbuf + pp*256;
        #pragma unroll
        for (int d = 0; d < 16; d++) {
            const float4* wr = (const float4*)(wg + d*16);
            float a = 0.f;
            #pragma unroll
            for (int q4 = 0; q4 < 4; q4++) {
                float4 wv = wr[q4];
                a += wv.x*hv[q4*4] + wv.y*hv[q4*4+1] + wv.z*hv[q4*4+2] + wv.w*hv[q4*4+3];
            }
            v2[d] = a;
        }

        float lg[9];
        #pragma unroll
        for (int q = 0; q < 9; q++) {
            const float4* u = (const float4*)&svt[q*16];
            float4 u0 = u[0], u1 = u[1], u2 = u[2], u3 = u[3];
            float a = u0.x*v2[0]  + u0.y*v2[1]  + u0.z*v2[2]  + u0.w*v2[3]
                    + u1.x*v2[4]  + u1.y*v2[5]  + u1.z*v2[6]  + u1.w*v2[7]
                    + u2.x*v2[8]  + u2.y*v2[9]  + u2.z*v2[10] + u2.w*v2[11]
                    + u3.x*v2[12] + u3.y*v2[13] + u3.z*v2[14] + u3.w*v2[15];
            lg[q] = a * sc;
        }
        float m = lg[0];
        #pragma unroll
        for (int q = 1; q < 9; q++) m = fmaxf(m, lg[q]);
        float s = 0.f;
        #pragma unroll
        for (int q = 0; q < 9; q++) { lg[q] = __expf(lg[q] - m); s += lg[q]; }
        float inv = 1.f / s;
        #pragma unroll
        for (int q = 0; q < 9; q++) att[pp*9+q] = lg[q] * inv;
    }
    __syncthreads();
    for (int j = tid; j < 2304; j += BTH) wbuf[j] = w3[j];
    __syncthreads();

    // ---- Phase 3: v3[g] overwrites private smem ----
    #pragma unroll 1
    for (int g = 0; g < 9; g++) {
        int yy = y + shift*c_dy[g];
        int xx = x + shift*c_dx[g];
        bool inb = ((unsigned)yy < (unsigned)IMGH) && ((unsigned)xx < (unsigned)IMGW);
        float sgn = (g < 8) ? -1.f : 1.f;
        const float* hp = hb + yy*IMGW + xx;
        #pragma unroll
        for (int c = 0; c < 16; c++)
            hv[c] = inb ? sgn*__ldg(&hp[(size_t)c*HW]) : 0.f;

        const float* wg = wbuf + g*256;
        #pragma unroll
        for (int d4 = 0; d4 < 4; d4++) {
            float t[4];
            #pragma unroll
            for (int dd = 0; dd < 4; dd++) {
                const float4* wr = (const float4*)(wg + (d4*4+dd)*16);
                float a = 0.f;
                #pragma unroll
                for (int q4 = 0; q4 < 4; q4++) {
                    float4 wv = wr[q4];
                    a += wv.x*hv[q4*4] + wv.y*hv[q4*4+1] + wv.z*hv[q4*4+2] + wv.w*hv[q4*4+3];
                }
                t[dd] = a;
            }
            *(float4*)&svt[g*16 + d4*4] = make_float4(t[0],t[1],t[2],t[3]);
        }
    }

    // ---- Phase 4: out[p] = sum_q att[p][q] * v3[q] ----
    float* catb = g_cat + (size_t)bb*CCAT*HW + (size_t)cbase*HW + p;
    #pragma unroll 1
    for (int pp = 0; pp < 9; pp++) {
        float oa[16];
        #pragma unroll
        for (int c = 0; c < 16; c++) oa[c] = 0.f;
        #pragma unroll
        for (int q = 0; q < 9; q++) {
            float a = att[pp*9+q];
            const float4* u = (const float4*)&svt[q*16];
            float4 u0 = u[0], u1 = u[1], u2 = u[2], u3 = u[3];
            oa[0]  += a*u0.x; oa[1]  += a*u0.y; oa[2]  += a*u0.z; oa[3]  += a*u0.w;
            oa[4]  += a*u1.x; oa[5]  += a*u1.y; oa[6]  += a*u1.z; oa[7]  += a*u1.w;
            oa[8]  += a*u2.x; oa[9]  += a*u2.y; oa[10] += a*u2.z; oa[11] += a*u2.w;
            oa[12] += a*u3.x; oa[13] += a*u3.y; oa[14] += a*u3.z; oa[15] += a*u3.w;
        }
        #pragma unroll
        for (int c = 0; c < 16; c++)
            catb[(size_t)(pp*16 + c)*HW] = oa[c];
    }
}

// ---------------- K5: final 1x1 conv 288->128, o-split x2, MLP=4 ---------
// grid (HB*HW/128, 2); 256 thr; thread tile 4px x 8outs; smem 80.6KB -> 2 CTA.
__global__ void __launch_bounds__(256)
k_out(const float* __restrict__ wo, const float* __restrict__ bo,
      float* __restrict__ out)
{
    extern __shared__ float ws[];                // [288][70], o-contiguous
    int tid = threadIdx.x;
    int obase = blockIdx.y*64;
    for (int j = tid; j < 288*64; j += 256) {
        int o = j / 288, i = j - o*288;          // coalesced global read
        ws[i*70 + o] = __ldg(&wo[(size_t)(obase+o)*CCAT + i]);
    }
    __syncthreads();

    int out_t = tid >> 5;                        // 0..7 -> 8 outs each
    int px_t  = tid & 31;
    int o0 = out_t*8;
    int gpx = blockIdx.x*128 + px_t*4;
    int bb = gpx / HW, p0 = gpx - bb*HW;
    const float* cp = g_cat + (size_t)bb*CCAT*HW + p0;

    ull acc[4][4];
    #pragma unroll
    for (int px = 0; px < 4; px++)
        #pragma unroll
        for (int pr = 0; pr < 4; pr++) acc[px][pr] = 0ull;

    float4 xq[4];
    #pragma unroll
    for (int d = 0; d < 4; d++) xq[d] = __ldg((const float4*)(cp + (size_t)d*HW));

    for (int i0 = 0; i0 < CCAT; i0 += 4) {
        #pragma unroll
        for (int u = 0; u < 4; u++) {
            int i = i0 + u;
            float4 xv = xq[u];
            if (i + 4 < CCAT) xq[u] = __ldg((const float4*)(cp + (size_t)(i+4)*HW));
            ull xp0, xp1, xp2, xp3;
            PACK2(xp0, xv.x, xv.x);
            PACK2(xp1, xv.y, xv.y);
            PACK2(xp2, xv.z, xv.z);
            PACK2(xp3, xv.w, xv.w);
            const ull* wp = (const ull*)&ws[i*70 + o0];
            #pragma unroll
            for (int pr = 0; pr < 4; pr++) {
                ull wv = wp[pr];
                FMA2(acc[0][pr], wv, xp0);
                FMA2(acc[1][pr], wv, xp1);
                FMA2(acc[2][pr], wv, xp2);
                FMA2(acc[3][pr], wv, xp3);
            }
        }
    }

    float* ob = out + (size_t)bb*COUT*HW + p0;
    #pragma unroll
    for (int pr = 0; pr < 4; pr++) {
        float lo[4], hi[4];
        #pragma unroll
        for (int px = 0; px < 4; px++) UNPACK2(lo[px], hi[px], acc[px][pr]);
        int o = obase + o0 + 2*pr;
        float bv0 = __ldg(&bo[o]);
        float bv1 = __ldg(&bo[o+1]);
        *(float4*)&ob[(size_t)(o  )*HW] = make_float4(lo[0]+bv0, lo[1]+bv0, lo[2]+bv0, lo[3]+bv0);
        *(float4*)&ob[(size_t)(o+1)*HW] = make_float4(hi[0]+bv1, hi[1]+bv1, hi[2]+bv1, hi[3]+bv1);
    }
}

// ---------------- launcher ----------------
extern "C" void kernel_launch(void* const* d_in, const int* in_sizes, int n_in,
                              void* d_out, int out_size)
{
    const float* cen   = (const float*)d_in[0];
    const float* in_w0 = (const float*)d_in[1];
    const float* in_b0 = (const float*)d_in[2];
    const float* in_w1 = (const float*)d_in[3];
    const float* in_b1 = (const float*)d_in[4];
    const float* w1_0  = (const float*)d_in[5];
    const float* w2_0  = (const float*)d_in[6];
    const float* w3_0  = (const float*)d_in[7];
    const float* w1_1  = (const float*)d_in[8];
    const float* w2_1  = (const float*)d_in[9];
    const float* w3_1  = (const float*)d_in[10];
    const float* scale = (const float*)d_in[11];
    const float* out_w = (const float*)d_in[12];
    const float* out_b = (const float*)d_in[13];
    float* out = (float*)d_out;

    size_t br_smem  = (size_t)(2304 + BTH*PADV + BTH*PADA)*sizeof(float); // 97920 B
    size_t out_smem = (size_t)288*70*sizeof(float);                       // 80640 B
    cudaFuncSetAttribute(k_branch, cudaFuncAttributeMaxDynamicSharedMemorySize,
                         (int)br_smem);
    cudaFuncSetAttribute(k_out, cudaFuncAttributeMaxDynamicSharedMemorySize,
                         (int)out_smem);

    k_prep<<<(CIN*288)/256, 256>>>(in_w1);
    k_conv1x1<<<HB*HW/256, 256>>>(cen, in_w0, in_b0);
    k_conv3x3<<<dim3(IMGW/64, IMGH/16, HB), dim3(16, 16)>>>(cen, in_b1);
    k_branch<<<HB*HW/BTH, BTH, br_smem>>>(0, w1_0, w2_0, w3_0, scale, 0, 1, 0);
    k_branch<<<HB*HW/BTH, BTH, br_smem>>>(1, w1_1, w2_1, w3_1, scale, 1, 5, 144);
    k_out<<<dim3(HB*HW/128, 2), 256, out_smem>>>(out_w, out_b, out);
}

// round 5
// speedup vs baseline: 2.2383x; 1.4493x over previous
#include <cuda_runtime.h>
#include <cuda_fp16.h>
#include <cstdint>

#define HB   4
#define CIN  256
#define HID  16
#define IMGH 192
#define IMGW 192
#define HW   (IMGH*IMGW)        // 36864
#define COUT 128
#define CCAT 288

typedef unsigned int uint;
typedef unsigned long long ull;
#define FMA2(acc,a,b)  asm("fma.rn.f32x2 %0, %1, %2, %0;" : "+l"(acc) : "l"(a), "l"(b))
#define PACK2(d,lo,hi) asm("mov.b64 %0, {%1, %2};" : "=l"(d) : "f"(lo), "f"(hi))
#define UNPACK2(lo,hi,s) asm("mov.b64 {%0, %1}, %2;" : "=f"(lo), "=f"(hi) : "l"(s))

// ---------------- scratch (device globals; no allocation) ----------------
__device__ float  g_h[2][HB*HID*HW];       // h0, h1 (fp32, branch input)
__device__ float  g_cat[HB*CCAT*HW];       // branch outputs concatenated (fp32)
__device__ __half g_wkh[10*16*256];        // [tap(9=1x1)][o][ci] hi
__device__ __half g_wkl[10*16*256];        // lo
__device__ __half g_woh[COUT*CCAT];        // [o][i] hi
__device__ __half g_wol[COUT*CCAT];        // lo

__constant__ int c_dy[9] = {-1,-1,-1, 0, 1, 1, 1, 0, 0};
__constant__ int c_dx[9] = {-1, 0, 1, 1, 1, 0,-1,-1, 0};

__device__ __forceinline__ void h2split(float v, __half& h, __half& l)
{
    h = __float2half_rn(v);
    l = __float2half_rn(v - __half2float(h));
}
__device__ __forceinline__ uint lduh(const __half* p) { return *(const uint*)p; }

__device__ __forceinline__ void mma16816(float* d,
                                         uint a0, uint a1, uint a2, uint a3,
                                         uint b0, uint b1)
{
    asm volatile("mma.sync.aligned.m16n8k16.row.col.f32.f16.f16.f32 "
        "{%0,%1,%2,%3}, {%4,%5,%6,%7}, {%8,%9}, {%0,%1,%2,%3};"
        : "+f"(d[0]), "+f"(d[1]), "+f"(d[2]), "+f"(d[3])
        : "r"(a0), "r"(a1), "r"(a2), "r"(a3), "r"(b0), "r"(b1));
}

// ---------------- prep: split weights into f16 hi/lo ----------------
__global__ void k_prep(const float* __restrict__ w3,    // in_w1 (16,256,3,3)
                       const float* __restrict__ w1,    // in_w0 (16,256,1,1)
                       const float* __restrict__ wo)    // out_w (128,288,1,1)
{
    int idx = blockIdx.x*256 + threadIdx.x;
    const int N1 = 10*16*256;
    if (idx < N1) {
        int t  = idx >> 12;
        int o  = (idx >> 8) & 15;
        int ci = idx & 255;
        float v = (t < 9) ? w3[(o*256 + ci)*9 + t] : w1[o*256 + ci];
        __half h, l; h2split(v, h, l);
        g_wkh[idx] = h; g_wkl[idx] = l;
    } else if (idx < N1 + COUT*CCAT) {
        int j = idx - N1;
        float v = wo[j];
        __half h, l; h2split(v, h, l);
        g_woh[j] = h; g_wol[j] = l;
    }
}

// ---------------- K1: fused conv1x1 + conv3x3 via HMMA ----------------
// CTA tile: 64x x 4y px; 8 warps = (xh 0..1) x (y 0..3); warp: 32px x 16o.
// 10 "taps": 9 shifted (3x3) -> h1, tap 9 center -> h0. K chunks of 32 ci.
// A: cen f32 -> f16 hi/lo smem tile [6y][72x][36k]. B: [10][16][36k] hi/lo.
#define A_PLANE 15552
#define B_PLANE 5760
__global__ void __launch_bounds__(256)
k_conv_mma(const float* __restrict__ cen,
           const float* __restrict__ b0v,
           const float* __restrict__ b1v)
{
    extern __shared__ __half smc[];
    __half* Ah = smc;
    __half* Al = Ah + A_PLANE;
    __half* Bh = Al + A_PLANE;
    __half* Bl = Bh + B_PLANE;

    int tid  = threadIdx.x;
    int lane = tid & 31;
    int wid  = tid >> 5;
    int y_l  = wid & 3;
    int xh   = wid >> 2;

    int bx = blockIdx.x % 3;
    int yt = (blockIdx.x / 3) % 48;
    int bb = blockIdx.x / 144;
    int x0 = bx*64, y0 = yt*4;

    const int tdy[10] = {-1,-1,-1, 0, 0, 0, 1, 1, 1, 0};
    const int tdx[10] = {-1, 0, 1,-1, 0, 1,-1, 0, 1, 0};

    float acc1[2][2][4];     // h1 (3x3)
    float acc0[2][2][4];     // h0 (1x1)
    #pragma unroll
    for (int mt = 0; mt < 2; mt++)
        #pragma unroll
        for (int nt = 0; nt < 2; nt++)
            #pragma unroll
            for (int i = 0; i < 4; i++) { acc1[mt][nt][i] = 0.f; acc0[mt][nt][i] = 0.f; }

    // per-thread fragment bases
    int g  = lane >> 2;
    int k0 = 2*(lane & 3);
    // A element index = (sy*72 + sx)*36 + k ; sy = y_l+1+dy ; sx = xh*32 + r + 1 + dx
    int e0 = ((y_l + 1)*72 + (xh*32 + g + 1))*36;   // r = g base; +mt*16*36; +8*36

    for (int ci0 = 0; ci0 < CIN; ci0 += 32) {
        __syncthreads();
        // ---- stage A (cen tile, f32 -> hi/lo f16) ----
        for (int j = tid; j < 32*6*68; j += 256) {
            int sx = j % 68;
            int r2 = j / 68;
            int sy = r2 % 6;
            int ci = r2 / 6;
            int gy = y0 - 1 + sy, gx = x0 - 1 + sx;
            float v = 0.f;
            if ((unsigned)gy < (unsigned)IMGH && (unsigned)gx < (unsigned)IMGW)
                v = __ldg(&cen[((size_t)(bb*CIN + ci0 + ci))*HW + gy*IMGW + gx]);
            __half h, l; h2split(v, h, l);
            int a = (sy*72 + sx)*36 + ci;
            Ah[a] = h; Al[a] = l;
        }
        // ---- stage B (weights) ----
        for (int j = tid; j < 10*16*32; j += 256) {
            int ci = j & 31;
            int o  = (j >> 5) & 15;
            int t  = j >> 9;
            int gsrc = (t*16 + o)*256 + ci0 + ci;
            int a = (t*16 + o)*36 + ci;
            Bh[a] = g_wkh[gsrc];
            Bl[a] = g_wkl[gsrc];
        }
        __syncthreads();

        #pragma unroll 1
        for (int t = 0; t < 10; t++) {
            int aoff = (tdy[t]*72 + tdx[t])*36;
            #pragma unroll
            for (int ks = 0; ks < 32; ks += 16) {
                uint bh[2][2], bl[2][2];
                #pragma unroll
                for (int nt = 0; nt < 2; nt++) {
                    int bbase = (t*16 + nt*8 + g)*36 + ks + k0;
                    bh[nt][0] = lduh(&Bh[bbase]);     bh[nt][1] = lduh(&Bh[bbase+8]);
                    bl[nt][0] = lduh(&Bl[bbase]);     bl[nt][1] = lduh(&Bl[bbase+8]);
                }
                #pragma unroll
                for (int mt = 0; mt < 2; mt++) {
                    int ab = e0 + aoff + mt*16*36 + ks + k0;
                    uint ah0 = lduh(&Ah[ab]),         ah1 = lduh(&Ah[ab+8*36]);
                    uint ah2 = lduh(&Ah[ab+8]),       ah3 = lduh(&Ah[ab+8*36+8]);
                    uint al0 = lduh(&Al[ab]),         al1 = lduh(&Al[ab+8*36]);
                    uint al2 = lduh(&Al[ab+8]),       al3 = lduh(&Al[ab+8*36+8]);
                    float (*acc)[4] = (t < 9) ? acc1[mt] : acc0[mt];
                    #pragma unroll
                    for (int nt = 0; nt < 2; nt++) {
                        mma16816(acc[nt], ah0, ah1, ah2, ah3, bh[nt][0], bh[nt][1]);
                        mma16816(acc[nt], ah0, ah1, ah2, ah3, bl[nt][0], bl[nt][1]);
                        mma16816(acc[nt], al0, al1, al2, al3, bh[nt][0], bh[nt][1]);
                    }
                }
            }
        }
    }

    // ---- epilogue: write h0, h1 fp32 (+bias) ----
    #pragma unroll
    for (int mt = 0; mt < 2; mt++) {
        #pragma unroll
        for (int nt = 0; nt < 2; nt++) {
            #pragma unroll
            for (int i = 0; i < 4; i++) {
                int o  = nt*8 + 2*(lane & 3) + (i & 1);
                int gx = x0 + xh*32 + mt*16 + (lane >> 2) + ((i >= 2) ? 8 : 0);
                int gy = y0 + y_l;
                size_t ofs = ((size_t)(bb*HID + o))*HW + gy*IMGW + gx;
                g_h[1][ofs] = acc1[mt][nt][i] + __ldg(&b1v[o]);
                g_h[0][ofs] = acc0[mt][nt][i] + __ldg(&b0v[o]);
            }
        }
    }
}

// ---------------- K3/K4: branch (unchanged from R4) ----------------
#define PADV 148
#define PADA 83
#define BTH  96
__global__ void __launch_bounds__(BTH)
k_branch(int which,
         const float* __restrict__ w1, const float* __restrict__ w2,
         const float* __restrict__ w3, const float* __restrict__ scale,
         int sidx, int shift, int cbase)
{
    extern __shared__ float sm[];
    float* wbuf = sm;                    // 2304
    float* sv   = sm + 2304;             // BTH * PADV
    float* atm  = sm + 2304 + BTH*PADV;  // BTH * PADA

    int tid = threadIdx.x;
    for (int j = tid; j < 2304; j += BTH) wbuf[j] = w1[j];
    __syncthreads();

    int gid = blockIdx.x*BTH + tid;
    int bb = gid / HW, p = gid - bb*HW;
    int y = p / IMGW, x = p - y*IMGW;
    const float* hb = g_h[which] + (size_t)bb*HID*HW;
    float* svt = sv + tid*PADV;
    float* att = atm + tid*PADA;

    float hv[16];

    #pragma unroll 1
    for (int g = 0; g < 9; g++) {
        int yy = y + shift*c_dy[g];
        int xx = x + shift*c_dx[g];
        bool inb = ((unsigned)yy < (unsigned)IMGH) && ((unsigned)xx < (unsigned)IMGW);
        float sgn = (g < 8) ? -1.f : 1.f;
        const float* hp = hb + yy*IMGW + xx;
        #pragma unroll
        for (int c = 0; c < 16; c++)
            hv[c] = inb ? sgn*__ldg(&hp[(size_t)c*HW]) : 0.f;

        const float* wg = wbuf + g*256;
        #pragma unroll
        for (int d4 = 0; d4 < 4; d4++) {
            float t[4];
            #pragma unroll
            for (int dd = 0; dd < 4; dd++) {
                const float4* wr = (const float4*)(wg + (d4*4+dd)*16);
                float a = 0.f;
                #pragma unroll
                for (int q4 = 0; q4 < 4; q4++) {
                    float4 wv = wr[q4];
                    a += wv.x*hv[q4*4] + wv.y*hv[q4*4+1] + wv.z*hv[q4*4+2] + wv.w*hv[q4*4+3];
                }
                t[dd] = a;
            }
            *(float4*)&svt[g*16 + d4*4] = make_float4(t[0],t[1],t[2],t[3]);
        }
    }
    __syncthreads();
    for (int j = tid; j < 2304; j += BTH) wbuf[j] = w2[j];
    __syncthreads();

    float sc = __ldg(&scale[sidx]);

    #pragma unroll 1
    for (int pp = 0; pp < 9; pp++) {
        int yy = y + shift*c_dy[pp];
        int xx = x + shift*c_dx[pp];
        bool inb = ((unsigned)yy < (unsigned)IMGH) && ((unsigned)xx < (unsigned)IMGW);
        float sgn = (pp < 8) ? -1.f : 1.f;
        const float* hp = hb + yy*IMGW + xx;
        #pragma unroll
        for (int c = 0; c < 16; c++)
            hv[c] = inb ? sgn*__ldg(&hp[(size_t)c*HW]) : 0.f;

        float v2[16];
        const float* wg = wbuf + pp*256;
        #pragma unroll
        for (int d = 0; d < 16; d++) {
            const float4* wr = (const float4*)(wg + d*16);
            float a = 0.f;
            #pragma unroll
            for (int q4 = 0; q4 < 4; q4++) {
                float4 wv = wr[q4];
                a += wv.x*hv[q4*4] + wv.y*hv[q4*4+1] + wv.z*hv[q4*4+2] + wv.w*hv[q4*4+3];
            }
            v2[d] = a;
        }

        float lg[9];
        #pragma unroll
        for (int q = 0; q < 9; q++) {
            const float4* u = (const float4*)&svt[q*16];
            float4 u0 = u[0], u1 = u[1], u2 = u[2], u3 = u[3];
            float a = u0.x*v2[0]  + u0.y*v2[1]  + u0.z*v2[2]  + u0.w*v2[3]
                    + u1.x*v2[4]  + u1.y*v2[5]  + u1.z*v2[6]  + u1.w*v2[7]
                    + u2.x*v2[8]  + u2.y*v2[9]  + u2.z*v2[10] + u2.w*v2[11]
                    + u3.x*v2[12] + u3.y*v2[13] + u3.z*v2[14] + u3.w*v2[15];
            lg[q] = a * sc;
        }
        float m = lg[0];
        #pragma unroll
        for (int q = 1; q < 9; q++) m = fmaxf(m, lg[q]);
        float s = 0.f;
        #pragma unroll
        for (int q = 0; q < 9; q++) { lg[q] = __expf(lg[q] - m); s += lg[q]; }
        float inv = 1.f / s;
        #pragma unroll
        for (int q = 0; q < 9; q++) att[pp*9+q] = lg[q] * inv;
    }
    __syncthreads();
    for (int j = tid; j < 2304; j += BTH) wbuf[j] = w3[j];
    __syncthreads();

    #pragma unroll 1
    for (int g = 0; g < 9; g++) {
        int yy = y + shift*c_dy[g];
        int xx = x + shift*c_dx[g];
        bool inb = ((unsigned)yy < (unsigned)IMGH) && ((unsigned)xx < (unsigned)IMGW);
        float sgn = (g < 8) ? -1.f : 1.f;
        const float* hp = hb + yy*IMGW + xx;
        #pragma unroll
        for (int c = 0; c < 16; c++)
            hv[c] = inb ? sgn*__ldg(&hp[(size_t)c*HW]) : 0.f;

        const float* wg = wbuf + g*256;
        #pragma unroll
        for (int d4 = 0; d4 < 4; d4++) {
            float t[4];
            #pragma unroll
            for (int dd = 0; dd < 4; dd++) {
                const float4* wr = (const float4*)(wg + (d4*4+dd)*16);
                float a = 0.f;
                #pragma unroll
                for (int q4 = 0; q4 < 4; q4++) {
                    float4 wv = wr[q4];
                    a += wv.x*hv[q4*4] + wv.y*hv[q4*4+1] + wv.z*hv[q4*4+2] + wv.w*hv[q4*4+3];
                }
                t[dd] = a;
            }
            *(float4*)&svt[g*16 + d4*4] = make_float4(t[0],t[1],t[2],t[3]);
        }
    }

    float* catb = g_cat + (size_t)bb*CCAT*HW + (size_t)cbase*HW + p;
    #pragma unroll 1
    for (int pp = 0; pp < 9; pp++) {
        float oa[16];
        #pragma unroll
        for (int c = 0; c < 16; c++) oa[c] = 0.f;
        #pragma unroll
        for (int q = 0; q < 9; q++) {
            float a = att[pp*9+q];
            const float4* u = (const float4*)&svt[q*16];
            float4 u0 = u[0], u1 = u[1], u2 = u[2], u3 = u[3];
            oa[0]  += a*u0.x; oa[1]  += a*u0.y; oa[2]  += a*u0.z; oa[3]  += a*u0.w;
            oa[4]  += a*u1.x; oa[5]  += a*u1.y; oa[6]  += a*u1.z; oa[7]  += a*u1.w;
            oa[8]  += a*u2.x; oa[9]  += a*u2.y; oa[10] += a*u2.z; oa[11] += a*u2.w;
            oa[12] += a*u3.x; oa[13] += a*u3.y; oa[14] += a*u3.z; oa[15] += a*u3.w;
        }
        #pragma unroll
        for (int c = 0; c < 16; c++)
            catb[(size_t)(pp*16 + c)*HW] = oa[c];
    }
}

// ---------------- K5: final 1x1 conv 288->128 via HMMA ----------------
// CTA: 128 px x 128 o, K=288 in 9 chunks of 32. 8 warps = (wm 0..3 px) x (wn 0..1 o).
__global__ void __launch_bounds__(256)
k_out_mma(const float* __restrict__ bo, float* __restrict__ out)
{
    __shared__ __half Ah[128*36], Al[128*36], Bh[128*36], Bl[128*36];

    int tid  = threadIdx.x;
    int lane = tid & 31;
    int wid  = tid >> 5;
    int wm   = wid >> 1;
    int wn   = wid & 1;

    int pg = blockIdx.x*128;
    int bb = pg / HW;
    int p0 = pg - bb*HW;
    const float* cb = g_cat + (size_t)bb*CCAT*HW + p0;

    float acc[2][8][4];
    #pragma unroll
    for (int mt = 0; mt < 2; mt++)
        #pragma unroll
        for (int nt = 0; nt < 8; nt++)
            #pragma unroll
            for (int i = 0; i < 4; i++) acc[mt][nt][i] = 0.f;

    int g  = lane >> 2;
    int k0 = 2*(lane & 3);

    for (int i0 = 0; i0 < CCAT; i0 += 32) {
        __syncthreads();
        // stage A: g_cat f32 -> hi/lo, transpose to [px][k]
        {
            int px = tid & 127;
            int c0 = tid >> 7;
            for (int c = c0; c < 32; c += 2) {
                float v = __ldg(&cb[(size_t)(i0 + c)*HW + px]);
                __half h, l; h2split(v, h, l);
                Ah[px*36 + c] = h; Al[px*36 + c] = l;
            }
        }
        // stage B: pre-split weights [o][k]
        {
            int ch = tid & 31;
            int o0 = tid >> 5;
            for (int o = o0; o < COUT; o += 8) {
                int src = o*CCAT + i0 + ch;
                Bh[o*36 + ch] = g_woh[src];
                Bl[o*36 + ch] = g_wol[src];
            }
        }
        __syncthreads();

        #pragma unroll
        for (int ks = 0; ks < 32; ks += 16) {
            uint bh[8][2], bl[8][2];
            #pragma unroll
            for (int nt = 0; nt < 8; nt++) {
                int bbase = (wn*64 + nt*8 + g)*36 + ks + k0;
                bh[nt][0] = lduh(&Bh[bbase]); bh[nt][1] = lduh(&Bh[bbase+8]);
                bl[nt][0] = lduh(&Bl[bbase]); bl[nt][1] = lduh(&Bl[bbase+8]);
            }
            #pragma unroll
            for (int mt = 0; mt < 2; mt++) {
                int ab = (wm*32 + mt*16 + g)*36 + ks + k0;
                uint ah0 = lduh(&Ah[ab]),      ah1 = lduh(&Ah[ab+8*36]);
                uint ah2 = lduh(&Ah[ab+8]),    ah3 = lduh(&Ah[ab+8*36+8]);
                uint al0 = lduh(&Al[ab]),      al1 = lduh(&Al[ab+8*36]);
                uint al2 = lduh(&Al[ab+8]),    al3 = lduh(&Al[ab+8*36+8]);
                #pragma unroll
                for (int nt = 0; nt < 8; nt++) {
                    mma16816(acc[mt][nt], ah0, ah1, ah2, ah3, bh[nt][0], bh[nt][1]);
                    mma16816(acc[mt][nt], ah0, ah1, ah2, ah3, bl[nt][0], bl[nt][1]);
                    mma16816(acc[mt][nt], al0, al1, al2, al3, bh[nt][0], bh[nt][1]);
                }
            }
        }
    }

    float* ob = out + (size_t)bb*COUT*HW;
    #pragma unroll
    for (int mt = 0; mt < 2; mt++) {
        #pragma unroll
        for (int nt = 0; nt < 8; nt++) {
            #pragma unroll
            for (int i = 0; i < 4; i++) {
                int o  = wn*64 + nt*8 + 2*(lane & 3) + (i & 1);
                int px = p0 + wm*32 + mt*16 + (lane >> 2) + ((i >= 2) ? 8 : 0);
                ob[(size_t)o*HW + px] = acc[mt][nt][i] + __ldg(&bo[o]);
            }
        }
    }
}

// ---------------- launcher ----------------
extern "C" void kernel_launch(void* const* d_in, const int* in_sizes, int n_in,
                              void* d_out, int out_size)
{
    const float* cen   = (const float*)d_in[0];
    const float* in_w0 = (const float*)d_in[1];
    const float* in_b0 = (const float*)d_in[2];
    const float* in_w1 = (const float*)d_in[3];
    const float* in_b1 = (const float*)d_in[4];
    const float* w1_0  = (const float*)d_in[5];
    const float* w2_0  = (const float*)d_in[6];
    const float* w3_0  = (const float*)d_in[7];
    const float* w1_1  = (const float*)d_in[8];
    const float* w2_1  = (const float*)d_in[9];
    const float* w3_1  = (const float*)d_in[10];
    const float* scale = (const float*)d_in[11];
    const float* out_w = (const float*)d_in[12];
    const float* out_b = (const float*)d_in[13];
    float* out = (float*)d_out;

    size_t cv_smem = (size_t)(2*A_PLANE + 2*B_PLANE)*sizeof(__half); // 85248 B
    size_t br_smem = (size_t)(2304 + BTH*PADV + BTH*PADA)*sizeof(float); // 97920 B
    cudaFuncSetAttribute(k_conv_mma, cudaFuncAttributeMaxDynamicSharedMemorySize,
                         (int)cv_smem);
    cudaFuncSetAttribute(k_branch, cudaFuncAttributeMaxDynamicSharedMemorySize,
                         (int)br_smem);

    int prep_n = 10*16*256 + COUT*CCAT;
    k_prep<<<(prep_n + 255)/256, 256>>>(in_w1, in_w0, out_w);
    k_conv_mma<<<576, 256, cv_smem>>>(cen, in_b0, in_b1);
    k_branch<<<HB*HW/BTH, BTH, br_smem>>>(0, w1_0, w2_0, w3_0, scale, 0, 1, 0);
    k_branch<<<HB*HW/BTH, BTH, br_smem>>>(1, w1_1, w2_1, w3_1, scale, 1, 5, 144);
    k_out_mma<<<HB*HW/128, 256>>>(out_b, out);
}